// round 9
// baseline (speedup 1.0000x reference)
#include <cuda_runtime.h>
#include <cstdint>

#define NS 65536
#define D  32
#define R  128
#define SP 8          // sample-pairs per lane (16 samples per group)
#define GPB 2         // groups per block (4 warps each -> 8 warps, 256 threads)

typedef unsigned long long ull;

// smem (bytes):
//   W    [D][R] f32 @ 0       (16384)
//   V    [D][R] f32 @ 16384   (16384)   v = -w*a
//   C    [D][R] f32 @ 32768   (16384)
//   bias [R]    f32 @ 49152   (512)
//   red  [GPB][SP][4 warps][ss2,pp2] @ 49664  (2*512 = 1024)
//   xt   [GPB][D][16] f32 @ 50688   (2*2048 = 4096)
#define OFF_V    16384
#define OFF_C    32768
#define OFF_BIAS 49152
#define OFF_RED  49664
#define OFF_X    50688
#define SMEM_BYTES 54784

__device__ float gWt[D * R];     // [d][r]  w = 1/(sqrt(2)*clamp(b,1e-8))
__device__ float gVt[D * R];     // [d][r]  -w*a
__device__ float gCt[D * R];     // [d][r]  c transposed
__device__ float gBias[R];

__global__ void anfis_precomp(const float* __restrict__ a,
                              const float* __restrict__ b,
                              const float* __restrict__ c) {
    int r = blockIdx.x, d = threadIdx.x;
    float av = a[r * D + d];
    float bv = fmaxf(b[r * D + d], 1e-8f);
    float w  = 0.70710678118654752f / bv;
    gWt[d * R + r] = w;
    gVt[d * R + r] = -w * av;
    gCt[d * R + r] = c[r * (D + 1) + d];
    if (d == 0) gBias[r] = c[r * (D + 1) + D];
}

__device__ __forceinline__ ull fma2(ull a, ull b, ull c) {
    ull d;
    asm("fma.rn.f32x2 %0, %1, %2, %3;" : "=l"(d) : "l"(a), "l"(b), "l"(c));
    return d;
}
__device__ __forceinline__ ull add2(ull a, ull b) {
    ull d;
    asm("add.rn.f32x2 %0, %1, %2;" : "=l"(d) : "l"(a), "l"(b));
    return d;
}
__device__ __forceinline__ ull mul2(ull a, ull b) {
    ull d;
    asm("mul.rn.f32x2 %0, %1, %2;" : "=l"(d) : "l"(a), "l"(b));
    return d;
}
#define LDSF(base, imm, f) \
    asm volatile("ld.shared.f32 %0, [%1 + %2];" : "=f"(f) : "r"(base), "n"(imm))
#define LDS128I(base, imm, lo, hi) \
    asm volatile("ld.shared.v2.u64 {%0, %1}, [%2 + %3];" \
                 : "=l"(lo), "=l"(hi) : "r"(base), "n"(imm))
__device__ __forceinline__ void sts128(uint32_t addr, ull lo, ull hi) {
    asm volatile("st.shared.v2.u64 [%0], {%1, %2};" :: "r"(addr), "l"(lo), "l"(hi));
}
__device__ __forceinline__ void unpack2(ull v, float& lo, float& hi) {
    asm("mov.b64 {%0, %1}, %2;" : "=f"(lo), "=f"(hi) : "l"(v));
}
__device__ __forceinline__ ull pack2(float lo, float hi) {
    ull v;
    asm("mov.b64 %0, {%1, %2};" : "=l"(v) : "f"(lo), "f"(hi));
    return v;
}
__device__ __forceinline__ ull shfl2(ull v, int off) {
    return __shfl_xor_sync(0xffffffffu, v, off);
}

// one d-step, compile-time immediates (k = d within 8-step chunk)
#define XS(k, p4)                                                   \
    {                                                               \
        ull xa, xc, u;                                              \
        LDS128I(xB, (k) * 64 + (p4) * 16, xa, xc);                  \
        u = fma2(w2, xa, v2);                                       \
        ag[2 * (p4)]     = fma2(u, u, ag[2 * (p4)]);                \
        al[2 * (p4)]     = fma2(c2, xa, al[2 * (p4)]);              \
        u = fma2(w2, xc, v2);                                       \
        ag[2 * (p4) + 1] = fma2(u, u, ag[2 * (p4) + 1]);            \
        al[2 * (p4) + 1] = fma2(c2, xc, al[2 * (p4) + 1]);          \
    }
#define STEP(k)                                                     \
    {                                                               \
        float w, v, cc;                                             \
        LDSF(cb, (k) * 512, w);                                     \
        LDSF(cb, (k) * 512 + OFF_V, v);                             \
        LDSF(cb, (k) * 512 + OFF_C, cc);                            \
        ull w2 = pack2(w, w), v2 = pack2(v, v), c2 = pack2(cc, cc); \
        XS(k, 0) XS(k, 1) XS(k, 2) XS(k, 3)                         \
    }

__global__ void __launch_bounds__(256, 4)
anfis_main(const float* __restrict__ X,
           float* __restrict__ pred,
           float* __restrict__ strengths,
           float* __restrict__ normalized) {
    extern __shared__ float smem[];
    uint32_t sbase;
    {
        uint64_t t;
        asm("cvta.to.shared.u64 %0, %1;" : "=l"(t) : "l"(smem));
        sbase = (uint32_t)t;
    }

    // fill coefficient tables: 3*4096 floats + bias, via float4
    {
        const float4* sw = reinterpret_cast<const float4*>(gWt);
        const float4* sv = reinterpret_cast<const float4*>(gVt);
        const float4* sc = reinterpret_cast<const float4*>(gCt);
        float4* dw = reinterpret_cast<float4*>(smem);
        float4* dv = reinterpret_cast<float4*>(smem + OFF_V / 4);
        float4* dc = reinterpret_cast<float4*>(smem + OFF_C / 4);
        #pragma unroll
        for (int i = 0; i < 4; i++) {
            int j = threadIdx.x + i * 256;
            dw[j] = sw[j];
            dv[j] = sv[j];
            dc[j] = sc[j];
        }
        if (threadIdx.x < R)
            smem[OFF_BIAS / 4 + threadIdx.x] = gBias[threadIdx.x];
    }
    // stage X transposed per group: xt[g][d][s], 16 samples per group
    {
        int t   = threadIdx.x;
        int gg  = t >> 7;           // group
        int idx = t & 127;
        int row = idx & 15;         // sample 0..15
        int seg = idx >> 4;         // float4 along D, 0..7
        int n0g = (blockIdx.x * GPB + gg) * 16;
        float4 v = *reinterpret_cast<const float4*>(X + (n0g + row) * D + seg * 4);
        float* xt = smem + OFF_X / 4 + gg * 512;
        xt[(seg * 4 + 0) * 16 + row] = v.x;
        xt[(seg * 4 + 1) * 16 + row] = v.y;
        xt[(seg * 4 + 2) * 16 + row] = v.z;
        xt[(seg * 4 + 3) * 16 + row] = v.w;
    }
    __syncthreads();

    const int lane = threadIdx.x & 31;
    const int warp = threadIdx.x >> 5;
    const int g    = warp >> 2;          // group in block
    const int q    = warp & 3;           // rule quarter
    const int r    = q * 32 + lane;      // this lane's rule
    const int n0   = (blockIdx.x * GPB + g) * 16;

    uint32_t cb = sbase + (q * 32 + lane) * 4;        // +512/d, +imm for V,C
    uint32_t xB = sbase + OFF_X + g * 2048;           // +64/d

    ull ag[SP], al[SP];
    #pragma unroll
    for (int p = 0; p < SP; p++) { ag[p] = 0ull; al[p] = 0ull; }

    #pragma unroll 1
    for (int dc = 0; dc < 4; dc++) {
        STEP(0) STEP(1) STEP(2) STEP(3) STEP(4) STEP(5) STEP(6) STEP(7)
        cb += 8 * 512;
        xB += 8 * 64;
    }

    // ---- epilogue
    float biasf;
    asm volatile("ld.shared.f32 %0, [%1];" : "=f"(biasf)
                 : "r"(sbase + OFF_BIAS + r * 4));
    const ull bias2 = pack2(biasf, biasf);
    const uint32_t redg = sbase + OFF_RED + g * 512;

    #pragma unroll
    for (int p = 0; p < SP; p++) {
        float e0, e1;
        unpack2(ag[p], e0, e1);
        float s0 = __expf(-e0), s1 = __expf(-e1);
        ull s2  = pack2(s0, s1);
        ull pr2 = mul2(s2, add2(al[p], bias2));
        ull ss2 = s2, pp2 = pr2;
        #pragma unroll
        for (int off = 16; off > 0; off >>= 1) {
            ss2 = add2(ss2, shfl2(ss2, off));
            pp2 = add2(pp2, shfl2(pp2, off));
        }
        if (lane == 0) sts128(redg + p * 64 + q * 16, ss2, pp2);
        ag[p] = s2;   // keep strengths for FIN
        strengths[(n0 + 2 * p)     * R + r] = s0;
        strengths[(n0 + 2 * p + 1) * R + r] = s1;
    }
    __syncthreads();

    #pragma unroll
    for (int p = 0; p < SP; p++) {
        ull sa, pa, sb, pb, sc, pc, sd, pd;
        LDS128I(redg, 0,  sa, pa);   // q=0  (offset p*64 added via base)
        LDS128I(redg, 16, sb, pb);
        LDS128I(redg, 32, sc, pc);
        LDS128I(redg, 48, sd, pd);
        // note: base must include p*64 — handled by redp below
        (void)sa;(void)pa;(void)sb;(void)pb;(void)sc;(void)pc;(void)sd;(void)pd;
        uint32_t redp = redg + p * 64;
        ull s01, p01, s23, p23, s45, p45, s67, p67;
        LDS128I(redp, 0,  s01, p01);
        LDS128I(redp, 16, s23, p23);
        LDS128I(redp, 32, s45, p45);
        LDS128I(redp, 48, s67, p67);
        ull sst = add2(add2(s01, s23), add2(s45, s67));
        ull ppt = add2(add2(p01, p23), add2(p45, p67));
        float ta, tb;
        unpack2(sst, ta, tb);
        float inva = 1.0f / (ta + 1e-8f);
        float invb = 1.0f / (tb + 1e-8f);
        float s0, s1;
        unpack2(ag[p], s0, s1);
        normalized[(n0 + 2 * p)     * R + r] = s0 * inva;
        normalized[(n0 + 2 * p + 1) * R + r] = s1 * invb;
        if (q == 0 && lane == 0) {
            float pa2, pb2;
            unpack2(ppt, pa2, pb2);
            pred[n0 + 2 * p]     = pa2 * inva;
            pred[n0 + 2 * p + 1] = pb2 * invb;
        }
    }
}

extern "C" void kernel_launch(void* const* d_in, const int* in_sizes, int n_in,
                              void* d_out, int out_size) {
    const float* X = (const float*)d_in[0];
    const float* a = (const float*)d_in[1];
    const float* b = (const float*)d_in[2];
    const float* c = (const float*)d_in[3];

    float* out        = (float*)d_out;
    float* pred       = out;
    float* strengths  = out + NS;
    float* normalized = out + NS + NS * R;

    static bool attr_set = false;
    if (!attr_set) {
        cudaFuncSetAttribute(anfis_main,
                             cudaFuncAttributeMaxDynamicSharedMemorySize,
                             SMEM_BYTES);
        attr_set = true;
    }

    anfis_precomp<<<R, D>>>(a, b, c);
    anfis_main<<<NS / (16 * GPB), 256, SMEM_BYTES>>>(X, pred, strengths, normalized);
}

// round 10
// speedup vs baseline: 1.1145x; 1.1145x over previous
#include <cuda_runtime.h>
#include <cstdint>

#define NS 65536
#define D  32
#define R  128
#define SP 4          // sample-pairs per lane -> 8 samples per block

typedef unsigned long long ull;

// global coefficient table, single base pointer + immediates:
//   W at +0, V at +16384B, C at +32768B   (each [d][r] f32)
__device__ float gTab[3 * D * R];
__device__ float gBias[R];

// static smem per block: xt[D][8] f32 (1024B) + red[4 pairs][4 warps][16B] (256B)
#define OFF_RED 1024

__global__ void anfis_precomp(const float* __restrict__ a,
                              const float* __restrict__ b,
                              const float* __restrict__ c) {
    int r = blockIdx.x, d = threadIdx.x;
    float av = a[r * D + d];
    float bv = fmaxf(b[r * D + d], 1e-8f);
    float w  = 0.70710678118654752f / bv;
    gTab[d * R + r]            = w;        // W
    gTab[4096 + d * R + r]     = -w * av;  // V
    gTab[8192 + d * R + r]     = c[r * (D + 1) + d];  // C
    if (d == 0) gBias[r] = c[r * (D + 1) + D];
}

__device__ __forceinline__ ull fma2(ull a, ull b, ull c) {
    ull d;
    asm("fma.rn.f32x2 %0, %1, %2, %3;" : "=l"(d) : "l"(a), "l"(b), "l"(c));
    return d;
}
__device__ __forceinline__ ull add2(ull a, ull b) {
    ull d;
    asm("add.rn.f32x2 %0, %1, %2;" : "=l"(d) : "l"(a), "l"(b));
    return d;
}
__device__ __forceinline__ ull mul2(ull a, ull b) {
    ull d;
    asm("mul.rn.f32x2 %0, %1, %2;" : "=l"(d) : "l"(a), "l"(b));
    return d;
}
#define LDGF(ptr, imm, f) \
    asm volatile("ld.global.nc.f32 %0, [%1 + %2];" : "=f"(f) : "l"(ptr), "n"(imm))
#define LDS128I(base, imm, lo, hi) \
    asm volatile("ld.shared.v2.u64 {%0, %1}, [%2 + %3];" \
                 : "=l"(lo), "=l"(hi) : "r"(base), "n"(imm))
__device__ __forceinline__ void sts128(uint32_t addr, ull lo, ull hi) {
    asm volatile("st.shared.v2.u64 [%0], {%1, %2};" :: "r"(addr), "l"(lo), "l"(hi));
}
__device__ __forceinline__ void unpack2(ull v, float& lo, float& hi) {
    asm("mov.b64 {%0, %1}, %2;" : "=f"(lo), "=f"(hi) : "l"(v));
}
__device__ __forceinline__ ull pack2(float lo, float hi) {
    ull v;
    asm("mov.b64 %0, {%1, %2};" : "=l"(v) : "f"(lo), "f"(hi));
    return v;
}
__device__ __forceinline__ ull shfl2(ull v, int off) {
    return __shfl_xor_sync(0xffffffffu, v, off);
}

// one d-step: 3 LDG (L1-hit) + 3 packs + 2 LDS.128 broadcast + 12 fma2
#define STEPD(d)                                                    \
    {                                                               \
        float w, v, cc;                                             \
        LDGF(cb, (d) * 512, w);                                     \
        LDGF(cb, (d) * 512 + 16384, v);                             \
        LDGF(cb, (d) * 512 + 32768, cc);                            \
        ull w2 = pack2(w, w), v2 = pack2(v, v), c2 = pack2(cc, cc); \
        ull x0, x1, x2, x3, u;                                      \
        LDS128I(xB, (d) * 32,      x0, x1);                         \
        LDS128I(xB, (d) * 32 + 16, x2, x3);                         \
        u = fma2(w2, x0, v2); ag0 = fma2(u, u, ag0); al0 = fma2(c2, x0, al0); \
        u = fma2(w2, x1, v2); ag1 = fma2(u, u, ag1); al1 = fma2(c2, x1, al1); \
        u = fma2(w2, x2, v2); ag2 = fma2(u, u, ag2); al2 = fma2(c2, x2, al2); \
        u = fma2(w2, x3, v2); ag3 = fma2(u, u, ag3); al3 = fma2(c2, x3, al3); \
    }

#define EPI(p, AG, AL)                                              \
    {                                                               \
        float e0, e1;                                               \
        unpack2(AG, e0, e1);                                        \
        float s0 = __expf(-e0), s1 = __expf(-e1);                   \
        ull s2 = pack2(s0, s1);                                     \
        strengths[(n0 + 2 * (p))     * R + r] = s0;                 \
        strengths[(n0 + 2 * (p) + 1) * R + r] = s1;                 \
        ull pp2 = mul2(s2, add2(AL, bias2));                        \
        ull ss2 = s2;                                               \
        _Pragma("unroll")                                           \
        for (int off = 16; off > 0; off >>= 1) {                    \
            ss2 = add2(ss2, shfl2(ss2, off));                       \
            pp2 = add2(pp2, shfl2(pp2, off));                       \
        }                                                           \
        if (lane == 0) sts128(redB + (p) * 64 + q * 16, ss2, pp2);  \
        AG = s2;                                                    \
    }

#define FIN(p, AG)                                                  \
    {                                                               \
        ull s01, p01, s23, p23, s45, p45, s67, p67;                 \
        LDS128I(redB, (p) * 64 + 0,  s01, p01);                     \
        LDS128I(redB, (p) * 64 + 16, s23, p23);                     \
        LDS128I(redB, (p) * 64 + 32, s45, p45);                     \
        LDS128I(redB, (p) * 64 + 48, s67, p67);                     \
        ull sst = add2(add2(s01, s23), add2(s45, s67));             \
        ull ppt = add2(add2(p01, p23), add2(p45, p67));             \
        float ta, tb;                                               \
        unpack2(sst, ta, tb);                                       \
        float inva = 1.0f / (ta + 1e-8f);                           \
        float invb = 1.0f / (tb + 1e-8f);                           \
        float s0, s1;                                               \
        unpack2(AG, s0, s1);                                        \
        normalized[(n0 + 2 * (p))     * R + r] = s0 * inva;         \
        normalized[(n0 + 2 * (p) + 1) * R + r] = s1 * invb;         \
        if (q == 0 && lane == 0) {                                  \
            float pa, pb;                                           \
            unpack2(ppt, pa, pb);                                   \
            pred[n0 + 2 * (p)]     = pa * inva;                     \
            pred[n0 + 2 * (p) + 1] = pb * invb;                     \
        }                                                           \
    }

__global__ void __launch_bounds__(128, 10)
anfis_main(const float* __restrict__ X,
           float* __restrict__ pred,
           float* __restrict__ strengths,
           float* __restrict__ normalized) {
    __shared__ float smem[(1024 + 256) / 4 + 32];
    uint32_t sbase;
    {
        uint64_t t;
        asm("cvta.to.shared.u64 %0, %1;" : "=l"(t) : "l"(smem));
        sbase = (uint32_t)t;
    }

    const int n0 = blockIdx.x * 8;      // 8 samples per block

    // stage X transposed: xt[d][s], 8 rows x 32 floats, 64 threads do 1 float4
    if (threadIdx.x < 64) {
        int row = threadIdx.x >> 3;     // 0..7
        int seg = threadIdx.x & 7;      // 0..7
        float4 v = *reinterpret_cast<const float4*>(X + (n0 + row) * D + seg * 4);
        smem[(seg * 4 + 0) * 8 + row] = v.x;
        smem[(seg * 4 + 1) * 8 + row] = v.y;
        smem[(seg * 4 + 2) * 8 + row] = v.z;
        smem[(seg * 4 + 3) * 8 + row] = v.w;
    }
    __syncthreads();

    const int lane = threadIdx.x & 31;
    const int q    = threadIdx.x >> 5;   // warp = rule quarter
    const int r    = q * 32 + lane;      // this lane's rule

    const float* cb = gTab + r;          // + d*512B, +16384B (V), +32768B (C)
    const uint32_t xB   = sbase;
    const uint32_t redB = sbase + OFF_RED;

    ull ag0 = 0, ag1 = 0, ag2 = 0, ag3 = 0;
    ull al0 = 0, al1 = 0, al2 = 0, al3 = 0;

    STEPD(0)  STEPD(1)  STEPD(2)  STEPD(3)  STEPD(4)  STEPD(5)  STEPD(6)  STEPD(7)
    STEPD(8)  STEPD(9)  STEPD(10) STEPD(11) STEPD(12) STEPD(13) STEPD(14) STEPD(15)
    STEPD(16) STEPD(17) STEPD(18) STEPD(19) STEPD(20) STEPD(21) STEPD(22) STEPD(23)
    STEPD(24) STEPD(25) STEPD(26) STEPD(27) STEPD(28) STEPD(29) STEPD(30) STEPD(31)

    float biasf;
    asm volatile("ld.global.nc.f32 %0, [%1];" : "=f"(biasf) : "l"(gBias + r));
    const ull bias2 = pack2(biasf, biasf);

    EPI(0, ag0, al0) EPI(1, ag1, al1) EPI(2, ag2, al2) EPI(3, ag3, al3)
    __syncthreads();
    FIN(0, ag0) FIN(1, ag1) FIN(2, ag2) FIN(3, ag3)
}

extern "C" void kernel_launch(void* const* d_in, const int* in_sizes, int n_in,
                              void* d_out, int out_size) {
    const float* X = (const float*)d_in[0];
    const float* a = (const float*)d_in[1];
    const float* b = (const float*)d_in[2];
    const float* c = (const float*)d_in[3];

    float* out        = (float*)d_out;
    float* pred       = out;
    float* strengths  = out + NS;
    float* normalized = out + NS + NS * R;

    anfis_precomp<<<R, D>>>(a, b, c);
    anfis_main<<<NS / 8, 128>>>(X, pred, strengths, normalized);
}